// round 16
// baseline (speedup 1.0000x reference)
#include <cuda_runtime.h>
#include <cuda_fp16.h>
#include <cstdint>
#include <cstddef>

#define HID        256
#define NNODES     50000
#define NEDGES     800000
#define NROWS_LBL  8192
#define SCAN_BLKS  196
#define GN_BLKS    391              // ceil(50000/128)
#define GL_BLKS    64               // 8192/128
#define CH0_BLKS   196              // GEMM chunk0 tiles
#define CH0_NODES  (CH0_BLKS * 128) // 25088
#define CH1_BLKS   (GN_BLKS - CH0_BLKS + GL_BLKS)  // 195 + 64 = 259

// ---------------- scratch ----------------
__device__ __half g_h [(size_t)NNODES * HID];
__device__ __half g_x16[(size_t)NNODES * HID];
__device__ __half g_wt[6 * 65536];
__device__ float g_beff[6 * 256];
__device__ int g_cnt[NNODES];
__device__ int g_flag[NNODES];
__device__ int g_off[NNODES + 1];
__device__ int g_eid[NEDGES];
__device__ int g_bsum[SCAN_BLKS];
__device__ int g_boff[SCAN_BLKS];

// ---------------- fused weight precompute ----------------
__global__ __launch_bounds__(256)
void fuse_w(const float* __restrict__ f0w, const float* __restrict__ f1w,
            const float* __restrict__ cw, __half* __restrict__ wt)
{
    __shared__ float sA[8][256];
    const int m = blockIdx.y;
    const int layer = m >> 1, which = m & 1;
    const float* A  = (which == 0 ? f0w : f1w) + (size_t)layer * 65536;
    const float* Wc = cw + (size_t)layer * 65536;
    const int k0 = blockIdx.x * 8;
    const int n  = threadIdx.x;

#pragma unroll
    for (int j = 0; j < 8; j++)
        sA[j][n] = A[(k0 + j) * 256 + n];
    __syncthreads();

    float acc[8];
#pragma unroll
    for (int j = 0; j < 8; j++) acc[j] = 0.f;

    for (int t = 0; t < 256; t++) {
        float wv = __ldg(&Wc[t * 256 + n]);
#pragma unroll
        for (int j = 0; j < 8; j++)
            acc[j] = fmaf(sA[j][t], wv, acc[j]);
    }
#pragma unroll
    for (int j = 0; j < 8; j++)
        wt[(size_t)m * 65536 + n * 256 + k0 + j] = __float2half_rn(acc[j]);
}

__global__ __launch_bounds__(256)
void fuse_b(const float* __restrict__ f0b, const float* __restrict__ f1b,
            const float* __restrict__ cw, const float* __restrict__ cb,
            float* __restrict__ beff)
{
    __shared__ float sB[256];
    const int m = blockIdx.x;
    const int layer = m >> 1, which = m & 1;
    const float* b  = (which == 0 ? f0b : f1b) + (size_t)layer * 256;
    const float* Wc = cw + (size_t)layer * 65536;
    const int n = threadIdx.x;
    sB[n] = b[n];
    __syncthreads();
    float acc = __ldg(&cb[layer * 256 + n]);
#pragma unroll 8
    for (int t = 0; t < 256; t++)
        acc = fmaf(sB[t], __ldg(&Wc[t * 256 + n]), acc);
    beff[m * 256 + n] = acc;
}

// ---------------- mma.sync fp16 GEMM, single pass, 3-stage pipeline ----------------
#define KC      32
#define LDS_A   40
#define TILE_HB (128 * LDS_A * 2)   // 10240 B
#define STAGE_B (2 * TILE_HB)       // 20480 B
#define NSTAGE  3

__device__ __forceinline__ void mma16816(float* c, const uint32_t* a, const uint32_t* b)
{
    asm volatile(
        "mma.sync.aligned.m16n8k16.row.col.f32.f16.f16.f32 "
        "{%0,%1,%2,%3}, {%4,%5,%6,%7}, {%8,%9}, {%0,%1,%2,%3};"
        : "+f"(c[0]), "+f"(c[1]), "+f"(c[2]), "+f"(c[3])
        : "r"(a[0]), "r"(a[1]), "r"(a[2]), "r"(a[3]), "r"(b[0]), "r"(b[1]));
}
__device__ __forceinline__ void ldm_x4(uint32_t* r, uint32_t addr)
{
    asm volatile("ldmatrix.sync.aligned.m8n8.x4.shared.b16 {%0,%1,%2,%3}, [%4];"
                 : "=r"(r[0]), "=r"(r[1]), "=r"(r[2]), "=r"(r[3]) : "r"(addr));
}
__device__ __forceinline__ void cpa16(uint32_t dst, const void* src, int sz)
{
    asm volatile("cp.async.ca.shared.global [%0], [%1], 16, %2;"
                 :: "r"(dst), "l"(src), "r"(sz));
}
__device__ __forceinline__ void cpa_commit() { asm volatile("cp.async.commit_group;"); }
template <int N>
__device__ __forceinline__ void cpa_wait() {
    asm volatile("cp.async.wait_group %0;" :: "n"(N));
}

// bx = blockIdx.x + blk_off over the merged [normal | labeled] tile space.
__global__ __launch_bounds__(256, 2)
void tc_gemm(const __half* __restrict__ A,
             const __half* __restrict__ Wt0, const __half* __restrict__ Wt1,
             const float* __restrict__ bias0, const float* __restrict__ bias1,
             __half* __restrict__ C,
             const int* __restrict__ pos, const int* __restrict__ flag,
             int blk_off)
{
    extern __shared__ __align__(16) char smem_dyn[];

    const int bx = blockIdx.x + blk_off;
    const bool lbl = (bx >= GN_BLKS);
    const __half* Wt  = lbl ? Wt1 : Wt0;
    const float* bias = lbl ? bias1 : bias0;
    const int* rowmap = lbl ? pos : nullptr;
    const int bm = (lbl ? (bx - GN_BLKS) : bx) * 128;

    const int tid  = threadIdx.x;
    const int wid  = tid >> 5;
    const int lane = tid & 31;
    const int bn   = blockIdx.y * 128;
    const int wr   = wid & 1;
    const int wc   = wid >> 1;
    const int qp = lane >> 2;
    const int qr = lane & 3;

    const uint32_t smem_u = (uint32_t)__cvta_generic_to_shared(smem_dyn);

    const int a_lr = (lane & 7) + ((lane >> 3) & 1) * 8;
    const int a_kc = ((lane >> 4) & 1) * 8;
    const int b_lr = (lane & 7) + ((lane >> 4) & 1) * 8;
    const int b_kc = ((lane >> 3) & 1) * 8;

    float acc[4][4][4];
#pragma unroll
    for (int i = 0; i < 4; i++)
#pragma unroll
        for (int j = 0; j < 4; j++)
#pragma unroll
            for (int r = 0; r < 4; r++) acc[i][j][r] = 0.f;

    int arow[2];
#pragma unroll
    for (int i = 0; i < 2; i++) {
        int u = i * 256 + tid;
        int r = u >> 2;
        int grow = bm + r;
        arow[i] = rowmap ? __ldg(&rowmap[grow]) : (grow < NNODES ? grow : -1);
    }

    auto load_stage = [&](int st, int k0) {
        const uint32_t sb = smem_u + st * STAGE_B;
#pragma unroll
        for (int i = 0; i < 2; i++) {
            int u = i * 256 + tid;
            int r = u >> 2;
            int cq = (u & 3);
            uint32_t doff = (uint32_t)(r * (LDS_A * 2) + cq * 16);
            int khalf = k0 + cq * 8;
            int sz = (arow[i] >= 0) ? 16 : 0;
            const __half* ga = A + ((size_t)(arow[i] >= 0 ? arow[i] : 0)) * HID + khalf;
            cpa16(sb + doff, ga, sz);
            cpa16(sb + TILE_HB + doff, Wt + (size_t)(bn + r) * HID + khalf, 16);
        }
    };

    auto compute_stage = [&](int st) {
        const uint32_t sA = smem_u + st * STAGE_B;
        const uint32_t sB = smem_u + st * STAGE_B + TILE_HB;
#pragma unroll
        for (int ks = 0; ks < KC; ks += 16) {
            uint32_t fA[4][4];
#pragma unroll
            for (int mt = 0; mt < 4; mt++) {
                uint32_t off = (uint32_t)(((wr * 64 + mt * 16 + a_lr) * LDS_A
                                           + ks + a_kc) * 2);
                ldm_x4(fA[mt], sA + off);
            }
            uint32_t fB[4][2];
#pragma unroll
            for (int j = 0; j < 2; j++) {
                uint32_t off = (uint32_t)(((wc * 32 + j * 16 + b_lr) * LDS_A
                                           + ks + b_kc) * 2);
                uint32_t r[4];
                ldm_x4(r, sB + off);
                fB[j * 2 + 0][0] = r[0]; fB[j * 2 + 0][1] = r[1];
                fB[j * 2 + 1][0] = r[2]; fB[j * 2 + 1][1] = r[3];
            }
#pragma unroll
            for (int mt = 0; mt < 4; mt++)
#pragma unroll
                for (int nt = 0; nt < 4; nt++)
                    mma16816(acc[mt][nt], fA[mt], fB[nt]);
        }
    };

    load_stage(0, 0);
    cpa_commit();
    load_stage(1, KC);
    cpa_commit();
#pragma unroll
    for (int c = 0; c < 8; c++) {
        if (c < 7) cpa_wait<1>(); else cpa_wait<0>();
        __syncthreads();
        if (c < 6) {
            load_stage((c + 2) % NSTAGE, (c + 2) * KC);
            cpa_commit();
        }
        compute_stage(c % NSTAGE);
    }

    // epilogue: fp16 output
#pragma unroll
    for (int mt = 0; mt < 4; mt++) {
        int grow0 = bm + wr * 64 + mt * 16 + qp;
        int grow1 = grow0 + 8;
        int row0, row1;
        bool v0, v1;
        if (lbl) {
            row0 = __ldg(&rowmap[grow0]);
            row1 = __ldg(&rowmap[grow1]);
            v0 = true; v1 = true;
        } else {
            row0 = grow0; row1 = grow1;
            v0 = (grow0 < NNODES) && (__ldg(&flag[grow0]) == 0);
            v1 = (grow1 < NNODES) && (__ldg(&flag[grow1]) == 0);
        }
#pragma unroll
        for (int nt = 0; nt < 4; nt++) {
            int col = bn + wc * 32 + nt * 8 + qr * 2;
            float b0 = __ldg(&bias[col]);
            float b1 = __ldg(&bias[col + 1]);
            if (v0) {
                __half2 o = __floats2half2_rn(acc[mt][nt][0] + b0, acc[mt][nt][1] + b1);
                *(__half2*)(C + (size_t)row0 * HID + col) = o;
            }
            if (v1) {
                __half2 o = __floats2half2_rn(acc[mt][nt][2] + b0, acc[mt][nt][3] + b1);
                *(__half2*)(C + (size_t)row1 * HID + col) = o;
            }
        }
    }
}

// ---------------- fp32 -> fp16 (initial x only) ----------------
__global__ void to_half(const float* __restrict__ in, __half* __restrict__ out, int n4)
{
    int t = blockIdx.x * blockDim.x + threadIdx.x;
    if (t >= n4) return;
    float4 v = ((const float4*)in)[t];
    __half2 h0 = __floats2half2_rn(v.x, v.y);
    __half2 h1 = __floats2half2_rn(v.z, v.w);
    uint2 o;
    o.x = *(uint32_t*)&h0;
    o.y = *(uint32_t*)&h1;
    ((uint2*)out)[t] = o;
}

// ---------------- CSR build + flags ----------------
__global__ void set_flag(const int* __restrict__ pos, int* __restrict__ flag)
{
    int t = blockIdx.x * blockDim.x + threadIdx.x;
    if (t < NROWS_LBL) flag[__ldg(&pos[t])] = 1;
}
__global__ void csr_hist(const int* __restrict__ dst, int* __restrict__ cnt)
{
    int t = blockIdx.x * blockDim.x + threadIdx.x;
    if (t < NEDGES) atomicAdd(&cnt[__ldg(&dst[t])], 1);
}
__global__ __launch_bounds__(256)
void scan_blk(const int* __restrict__ cnt, int* __restrict__ off, int* __restrict__ bsum)
{
    __shared__ int sh[256];
    int idx = blockIdx.x * 256 + threadIdx.x;
    int v = (idx < NNODES) ? cnt[idx] : 0;
    sh[threadIdx.x] = v;
    __syncthreads();
#pragma unroll
    for (int d = 1; d < 256; d <<= 1) {
        int t = (threadIdx.x >= d) ? sh[threadIdx.x - d] : 0;
        __syncthreads();
        sh[threadIdx.x] += t;
        __syncthreads();
    }
    if (idx < NNODES) off[idx] = sh[threadIdx.x] - v;
    if (threadIdx.x == 255) bsum[blockIdx.x] = sh[255];
}
__global__ __launch_bounds__(256)
void scan_top(const int* __restrict__ bsum, int* __restrict__ boff)
{
    __shared__ int sh[256];
    int v = (threadIdx.x < SCAN_BLKS) ? bsum[threadIdx.x] : 0;
    sh[threadIdx.x] = v;
    __syncthreads();
#pragma unroll
    for (int d = 1; d < 256; d <<= 1) {
        int t = (threadIdx.x >= d) ? sh[threadIdx.x - d] : 0;
        __syncthreads();
        sh[threadIdx.x] += t;
        __syncthreads();
    }
    if (threadIdx.x < SCAN_BLKS) boff[threadIdx.x] = sh[threadIdx.x] - v;
}
__global__ void scan_add(int* __restrict__ off, const int* __restrict__ boff,
                         int* __restrict__ cnt)
{
    int idx = blockIdx.x * 256 + threadIdx.x;
    if (idx < NNODES) {
        off[idx] += boff[blockIdx.x];
        cnt[idx] = 0;
    }
    if (idx == 0) off[NNODES] = NEDGES;
}
__global__ void csr_fill(const int* __restrict__ src, const int* __restrict__ dst,
                         const int* __restrict__ off, int* __restrict__ cur,
                         int* __restrict__ eid)
{
    int t = blockIdx.x * blockDim.x + threadIdx.x;
    if (t >= NEDGES) return;
    int d = __ldg(&dst[t]);
    int p = atomicAdd(&cur[d], 1);
    eid[__ldg(&off[d]) + p] = __ldg(&src[t]);
}

// ---------------- fp16 row accumulate helpers ----------------
__device__ __forceinline__ void acc_row(float* a, const __half* h, int e, int lane)
{
    uint4 q = __ldg(&((const uint4*)(h + (size_t)e * HID))[lane]);
    const __half2* hp = (const __half2*)&q;
#pragma unroll
    for (int j = 0; j < 4; j++) {
        float2 f = __half22float2(hp[j]);
        a[j * 2 + 0] += f.x;
        a[j * 2 + 1] += f.y;
    }
}

__device__ __forceinline__ void acc_segment(float* a, const __half* h,
                                            const int* eid, int s0, int s1, int lane)
{
    int i = s0;
    for (; i + 3 < s1; i += 4) {
        int e0 = __ldg(&eid[i]);
        int e1 = __ldg(&eid[i + 1]);
        int e2 = __ldg(&eid[i + 2]);
        int e3 = __ldg(&eid[i + 3]);
        acc_row(a, h, e0, lane);
        acc_row(a, h, e1, lane);
        acc_row(a, h, e2, lane);
        acc_row(a, h, e3, lane);
    }
    for (; i < s1; i++)
        acc_row(a, h, __ldg(&eid[i]), lane);
}

// ---------------- pull segment-sum over a node range, fp16 out ----------------
__global__ __launch_bounds__(256)
void pull_half(const __half* __restrict__ h, const int* __restrict__ off,
               const int* __restrict__ eid, __half* __restrict__ xo,
               int node_base, int node_end)
{
    int node = node_base + blockIdx.x * 8 + (threadIdx.x >> 5);
    if (node >= node_end) return;
    int lane = threadIdx.x & 31;
    int s0 = __ldg(&off[node]);
    int s1 = __ldg(&off[node + 1]);
    float a[8] = {0.f, 0.f, 0.f, 0.f, 0.f, 0.f, 0.f, 0.f};
    acc_segment(a, h, eid, s0, s1, lane);

    __half hv[8];
#pragma unroll
    for (int j = 0; j < 8; j++) hv[j] = __float2half_rn(a[j]);
    *(uint4*)(xo + (size_t)node * HID + lane * 8) = *(uint4*)hv;
}

// ---------------- last-layer pull: only pos rows, straight to d_out ----------------
__global__ __launch_bounds__(256)
void pull_out(const __half* __restrict__ h, const int* __restrict__ off,
              const int* __restrict__ eid, const int* __restrict__ pos,
              float* __restrict__ out)
{
    int slot = blockIdx.x * 8 + (threadIdx.x >> 5);
    if (slot >= NROWS_LBL) return;
    int lane = threadIdx.x & 31;
    int node = __ldg(&pos[slot]);
    int s0 = __ldg(&off[node]);
    int s1 = __ldg(&off[node + 1]);
    float a[8] = {0.f, 0.f, 0.f, 0.f, 0.f, 0.f, 0.f, 0.f};
    acc_segment(a, h, eid, s0, s1, lane);

    float4* O = (float4*)out + (size_t)slot * 64 + lane * 2;
    O[0] = make_float4(a[0], a[1], a[2], a[3]);
    O[1] = make_float4(a[4], a[5], a[6], a[7]);
}

// ---------------- launch ----------------
extern "C" void kernel_launch(void* const* d_in, const int* in_sizes, int n_in,
                              void* d_out, int out_size)
{
    (void)in_sizes; (void)n_in; (void)out_size;
    const float* x    = (const float*)d_in[0];
    const float* f0w  = (const float*)d_in[1];
    const float* f0b  = (const float*)d_in[2];
    const float* f1w  = (const float*)d_in[3];
    const float* f1b  = (const float*)d_in[4];
    const float* cw   = (const float*)d_in[5];
    const float* cb   = (const float*)d_in[6];
    const int*   esrc = (const int*)d_in[7];
    const int*   edst = (const int*)d_in[8];
    const int*   pos  = (const int*)d_in[9];

    float *beff;
    __half *h, *x16, *wt;
    int *cnt, *flag, *off, *eid, *bsum, *boff;
    cudaGetSymbolAddress((void**)&h,    g_h);
    cudaGetSymbolAddress((void**)&x16,  g_x16);
    cudaGetSymbolAddress((void**)&wt,   g_wt);
    cudaGetSymbolAddress((void**)&beff, g_beff);
    cudaGetSymbolAddress((void**)&cnt,  g_cnt);
    cudaGetSymbolAddress((void**)&flag, g_flag);
    cudaGetSymbolAddress((void**)&off,  g_off);
    cudaGetSymbolAddress((void**)&eid,  g_eid);
    cudaGetSymbolAddress((void**)&bsum, g_bsum);
    cudaGetSymbolAddress((void**)&boff, g_boff);

    const int SMEM_DYN = NSTAGE * STAGE_B;   // 61440
    static bool s_init = false;
    static cudaStream_t s1, s2;
    static cudaEvent_t ev_fork, ev_csr, ev_pre, evP[2], evG[2];
    if (!s_init) {
        cudaFuncSetAttribute(tc_gemm, cudaFuncAttributeMaxDynamicSharedMemorySize, SMEM_DYN);
        cudaStreamCreateWithFlags(&s1, cudaStreamNonBlocking);
        cudaStreamCreateWithFlags(&s2, cudaStreamNonBlocking);
        cudaEventCreateWithFlags(&ev_fork, cudaEventDisableTiming);
        cudaEventCreateWithFlags(&ev_csr,  cudaEventDisableTiming);
        cudaEventCreateWithFlags(&ev_pre,  cudaEventDisableTiming);
        for (int i = 0; i < 2; i++) {
            cudaEventCreateWithFlags(&evP[i], cudaEventDisableTiming);
            cudaEventCreateWithFlags(&evG[i], cudaEventDisableTiming);
        }
        s_init = true;
    }

    const int n4 = NNODES * HID / 4;
    const int pull_c0_blks = CH0_NODES / 8;                        // 3136
    const int pull_c1_blks = (NNODES - CH0_NODES + 7) / 8;         // 3114

    // ---- fork ----
    cudaEventRecord(ev_fork, 0);
    cudaStreamWaitEvent(s1, ev_fork, 0);
    cudaStreamWaitEvent(s2, ev_fork, 0);

    // s1: CSR chain
    cudaMemsetAsync(cnt, 0, NNODES * sizeof(int), s1);
    csr_hist<<<(NEDGES + 255) / 256, 256, 0, s1>>>(edst, cnt);
    scan_blk<<<SCAN_BLKS, 256, 0, s1>>>(cnt, off, bsum);
    scan_top<<<1, 256, 0, s1>>>(bsum, boff);
    scan_add<<<SCAN_BLKS, 256, 0, s1>>>(off, boff, cnt);
    csr_fill<<<(NEDGES + 255) / 256, 256, 0, s1>>>(esrc, edst, off, cnt, eid);
    cudaEventRecord(ev_csr, s1);

    // s2: flags + activation convert
    cudaMemsetAsync(flag, 0, NNODES * sizeof(int), s2);
    set_flag<<<(NROWS_LBL + 255) / 256, 256, 0, s2>>>(pos, flag);
    to_half<<<(n4 + 255) / 256, 256, 0, s2>>>(x, x16, n4);
    cudaEventRecord(ev_pre, s2);

    // main: fused weights
    fuse_w<<<dim3(32, 6), 256>>>(f0w, f1w, cw, wt);
    fuse_b<<<6, 256>>>(f0b, f1b, cw, cb, beff);
    cudaStreamWaitEvent(0, ev_pre, 0);

    // GEMM layer 0 (monolithic: x16 fully ready)
    {
        const size_t wo0 = 0, wo1 = 65536;
        tc_gemm<<<dim3(GN_BLKS + GL_BLKS, 2), 256, SMEM_DYN>>>(
            x16, wt + wo0, wt + wo1, beff + 0, beff + 256, h, pos, flag, 0);
    }
    cudaStreamWaitEvent(0, ev_csr, 0);

    // layer boundaries: pull(i) chunked, GEMM(i+1) chunked
    for (int i = 0; i < 2; i++) {
        const int L = i + 1;   // GEMM layer index
        const size_t wo0 = (size_t)(L * 2 + 0) * 65536;
        const size_t wo1 = (size_t)(L * 2 + 1) * 65536;
        const float* b0 = beff + (L * 2 + 0) * 256;
        const float* b1 = beff + (L * 2 + 1) * 256;

        // pull chunk0 (nodes [0, CH0_NODES)) then chunk1, on main
        pull_half<<<pull_c0_blks, 256>>>(h, off, eid, x16, 0, CH0_NODES);
        cudaEventRecord(evP[i], 0);
        pull_half<<<pull_c1_blks, 256>>>(h, off, eid, x16, CH0_NODES, NNODES);

        // GEMM chunk0 on s2 (needs only pull chunk0's rows)
        cudaStreamWaitEvent(s2, evP[i], 0);
        tc_gemm<<<dim3(CH0_BLKS, 2), 256, SMEM_DYN, s2>>>(
            x16, wt + wo0, wt + wo1, b0, b1, h, pos, flag, 0);
        cudaEventRecord(evG[i], s2);

        // GEMM chunk1 + labeled on main (after full pull by program order)
        tc_gemm<<<dim3(CH1_BLKS, 2), 256, SMEM_DYN>>>(
            x16, wt + wo0, wt + wo1, b0, b1, h, pos, flag, CH0_BLKS);
        cudaStreamWaitEvent(0, evG[i], 0);   // join before next pulls
    }

    pull_out<<<(NROWS_LBL + 7) / 8, 256>>>(h, off, eid, pos, (float*)d_out);
}